// round 12
// baseline (speedup 1.0000x reference)
#include <cuda_runtime.h>
#include <cuda_bf16.h>
#include <cstdint>
#include <math.h>
#include <float.h>

#define N_ROWS 32768
#define K_PROTO 1024
#define D_DIM 256
#define FIX_MARGIN 0.02f

// ---- scratch (device globals: no cudaMalloc allowed) ----
__device__ float          g_x2[N_ROWS];
__device__ float          g_p2[K_PROTO];
__device__ __nv_bfloat16  g_xhi[(size_t)N_ROWS * D_DIM];
__device__ __nv_bfloat16  g_phi[(size_t)K_PROTO * D_DIM];
__device__ float          g_ypart[1024 * K_PROTO];     // colsum(y) per CTA (4 MB)
__device__ float          g_vpart[1024 * K_PROTO];     // colsum(v) per CTA (4 MB)
__device__ double         g_lsepart[1024];             // sum(lse) per CTA
__device__ double         g_coly[K_PROTO];
__device__ double         g_colv[K_PROTO];

__device__ __forceinline__ uint32_t smem_u32(const void* p) {
    uint32_t a;
    asm("{ .reg .u64 t; cvta.to.shared.u64 t, %1; cvt.u32.u64 %0, t; }"
        : "=r"(a) : "l"(p));
    return a;
}
__device__ __forceinline__ void cp16(uint32_t saddr, const void* g) {
    asm volatile("cp.async.cg.shared.global [%0], [%1], 16;" :: "r"(saddr), "l"(g) : "memory");
}

// ===========================================================================
// K0: prep — warp per row: bf16 + row squared norm.
// ===========================================================================
__global__ void prep_kernel(const float* __restrict__ src,
                            __nv_bfloat16* __restrict__ hi,
                            float* __restrict__ sq, int rows)
{
    int warp = (blockIdx.x * blockDim.x + threadIdx.x) >> 5;
    int lane = threadIdx.x & 31;
    if (warp >= rows) return;
    const float4* s = (const float4*)(src + (size_t)warp * D_DIM);
    uint2* H = (uint2*)(hi + (size_t)warp * D_DIM);
    float acc = 0.f;
#pragma unroll
    for (int i = 0; i < 2; ++i) {
        int c = lane + 32 * i;
        float4 v = __ldg(&s[c]);
        acc += v.x * v.x + v.y * v.y + v.z * v.z + v.w * v.w;
        __nv_bfloat162 a; a.x = __float2bfloat16(v.x); a.y = __float2bfloat16(v.y);
        __nv_bfloat162 b; b.x = __float2bfloat16(v.z); b.y = __float2bfloat16(v.w);
        uint2 hv; hv.x = *(uint32_t*)&a; hv.y = *(uint32_t*)&b;
        H[c] = hv;
    }
#pragma unroll
    for (int off = 16; off; off >>= 1)
        acc += __shfl_xor_sync(0xffffffffu, acc, off);
    if (lane == 0) sq[warp] = acc;
}

// ===========================================================================
// K1: FUSED GEMM + softmax. CTA = 32 rows x full K=1024.
//     512 threads, 16 warps; warp w owns cols {w*32..} in each 512-col half.
//     B streamed from L2 in 8 stages (k-chunk x n-half), double buffered.
//     Epilogue: u=2dot+g-p2 in regs -> rowmax/argmax(+exact fixup)/exp/lse/
//     colsums/gather, all without logits touching DRAM.
// ===========================================================================
#define SM_A   0                       // 4 chunks x 32x128B = 16 KB
#define SM_B   16384                   // 2 bufs x 512x128B = 128 KB
#define SM_SCR (16384 + 131072)        // scratch
#define FUSED_SMEM (SM_SCR + 8192)     // ~152 KB

__device__ __forceinline__ void issue_stageB(int s, uint32_t sbase, int tid)
{
    const int c = s >> 1, h = s & 1;
    const uint32_t buf = sbase + SM_B + (uint32_t)(s & 1) * 65536;
#pragma unroll
    for (int it = 0; it < 8; ++it) {
        int i = tid + 512 * it;        // 0..4095
        int row = i >> 3, cc = i & 7;  // row 0..511
        cp16(buf + row * 128 + ((cc ^ (row & 7)) << 4),
             g_phi + (size_t)(h * 512 + row) * D_DIM + c * 64 + cc * 8);
    }
    asm volatile("cp.async.commit_group;" ::: "memory");
}

__global__ void __launch_bounds__(512, 1)
fused_kernel(const float* __restrict__ X, const float* __restrict__ P,
             const float* __restrict__ G, float* __restrict__ out)
{
    extern __shared__ __align__(128) char sm[];
    const uint32_t sbase = smem_u32(sm);
    const int tid  = threadIdx.x;
    const int w    = tid >> 5;
    const int lane = tid & 31;
    const int cta  = blockIdx.x;
    const int grow_base = cta * 32;

    float* rmax   = (float*)(sm + SM_SCR);        // [32][16]
    float* rsum   = rmax + 512;                   // [32][16]
    float* x2arr  = rsum + 512;                   // [32]
    float* marr   = x2arr + 32;                   // [32]
    float* invarr = marr + 32;                    // [32]
    float* lsearr = invarr + 32;                  // [32]
    int*   cnt    = (int*)(lsearr + 32);          // [32]
    int*   candk  = cnt + 32;                     // [32][16]

    // ---- prefetch: A (all 4 k-chunks, group 0 with B stage0), B stages 0,1
    {
#pragma unroll
        for (int it = 0; it < 2; ++it) {
            int i = tid + 512 * it;               // 0..1023
            int chunk = i >> 8, row = (i >> 3) & 31, cc = i & 7;
            cp16(sbase + SM_A + chunk * 4096 + row * 128 + ((cc ^ (row & 7)) << 4),
                 g_xhi + (size_t)(grow_base + row) * D_DIM + chunk * 64 + cc * 8);
        }
    }
    issue_stageB(0, sbase, tid);   // commits group 0 (A + B0)
    issue_stageB(1, sbase, tid);   // group 1

    float d[2][2][4][4];
#pragma unroll
    for (int mi = 0; mi < 2; ++mi)
#pragma unroll
        for (int h = 0; h < 2; ++h)
#pragma unroll
            for (int ni = 0; ni < 4; ++ni)
#pragma unroll
                for (int q = 0; q < 4; ++q) d[mi][h][ni][q] = 0.f;

    for (int s = 0; s < 8; ++s) {
        if (s < 7) asm volatile("cp.async.wait_group 1;" ::: "memory");
        else       asm volatile("cp.async.wait_group 0;" ::: "memory");
        __syncthreads();

        const int c = s >> 1, h = s & 1;
        const uint32_t bufA = sbase + SM_A + (uint32_t)c * 4096;
        const uint32_t bufB = sbase + SM_B + (uint32_t)(s & 1) * 65536;
#pragma unroll
        for (int ks = 0; ks < 4; ++ks) {
            uint32_t a[8], br[8];
#pragma unroll
            for (int mi = 0; mi < 2; ++mi) {
                int row = mi * 16 + (lane & 15);
                int cc  = ks * 2 + (lane >> 4);
                uint32_t ad = bufA + row * 128 + ((cc ^ (row & 7)) << 4);
                asm volatile("ldmatrix.sync.aligned.m8n8.x4.shared.b16 {%0,%1,%2,%3}, [%4];"
                    : "=r"(a[mi*4+0]), "=r"(a[mi*4+1]), "=r"(a[mi*4+2]), "=r"(a[mi*4+3])
                    : "r"(ad));
            }
#pragma unroll
            for (int p = 0; p < 2; ++p) {
                int nrow = w * 32 + p * 16 + ((lane >> 4) << 3) + (lane & 7);
                int cc   = ks * 2 + ((lane >> 3) & 1);
                uint32_t bd = bufB + nrow * 128 + ((cc ^ (nrow & 7)) << 4);
                asm volatile("ldmatrix.sync.aligned.m8n8.x4.shared.b16 {%0,%1,%2,%3}, [%4];"
                    : "=r"(br[p*4+0]), "=r"(br[p*4+1]), "=r"(br[p*4+2]), "=r"(br[p*4+3])
                    : "r"(bd));
            }
#pragma unroll
            for (int mi = 0; mi < 2; ++mi)
#pragma unroll
                for (int ni = 0; ni < 4; ++ni) {
                    asm volatile(
                        "mma.sync.aligned.m16n8k16.row.col.f32.bf16.bf16.f32 "
                        "{%0,%1,%2,%3}, {%4,%5,%6,%7}, {%8,%9}, {%0,%1,%2,%3};"
                        : "+f"(d[mi][h][ni][0]), "+f"(d[mi][h][ni][1]),
                          "+f"(d[mi][h][ni][2]), "+f"(d[mi][h][ni][3])
                        : "r"(a[mi*4+0]), "r"(a[mi*4+1]), "r"(a[mi*4+2]), "r"(a[mi*4+3]),
                          "r"(br[ni*2+0]), "r"(br[ni*2+1]));
                }
        }
        __syncthreads();
        if (s + 2 < 8) issue_stageB(s + 2, sbase, tid);
    }

    // ================= epilogue (all in-register, no logits DRAM) ==========
    if (tid < 32) { x2arr[tid] = __ldg(&g_x2[grow_base + tid]); cnt[tid] = 0; }
    __syncthreads();

    // u-phase: u = 2dot + g - p2 ; colsum(v=u-x2) ; per-row local max
    float cv[16];
#pragma unroll
    for (int q = 0; q < 16; ++q) cv[q] = 0.f;
    float mloc[4] = {-FLT_MAX, -FLT_MAX, -FLT_MAX, -FLT_MAX};
#pragma unroll
    for (int mi = 0; mi < 2; ++mi) {
        int r0 = mi * 16 + (lane >> 2);
        size_t grow0 = (size_t)(grow_base + r0) * K_PROTO;
        size_t grow1 = grow0 + 8 * K_PROTO;
        float x20 = x2arr[r0], x21 = x2arr[r0 + 8];
#pragma unroll
        for (int h = 0; h < 2; ++h)
#pragma unroll
            for (int ni = 0; ni < 4; ++ni) {
                int col = h * 512 + w * 32 + ni * 8 + (lane & 3) * 2;
                float2 p2v = *(const float2*)&g_p2[col];
                float2 ga = __ldg((const float2*)(G + grow0 + col));
                float2 gb = __ldg((const float2*)(G + grow1 + col));
                float* dd = d[mi][h][ni];
                float u0 = fmaf(2.f, dd[0], ga.x) - p2v.x;
                float u1 = fmaf(2.f, dd[1], ga.y) - p2v.y;
                float u2 = fmaf(2.f, dd[2], gb.x) - p2v.x;
                float u3 = fmaf(2.f, dd[3], gb.y) - p2v.y;
                dd[0] = u0; dd[1] = u1; dd[2] = u2; dd[3] = u3;
                int ci = h * 8 + ni * 2;
                cv[ci]     += (u0 - x20) + (u2 - x21);
                cv[ci + 1] += (u1 - x20) + (u3 - x21);
                mloc[mi * 2]     = fmaxf(mloc[mi * 2],     fmaxf(u0, u1));
                mloc[mi * 2 + 1] = fmaxf(mloc[mi * 2 + 1], fmaxf(u2, u3));
            }
    }
    // row max: reduce over 4 lanes sharing row, then across 16 warps
#pragma unroll
    for (int q = 0; q < 4; ++q) {
#pragma unroll
        for (int off = 1; off <= 2; off <<= 1)
            mloc[q] = fmaxf(mloc[q], __shfl_xor_sync(0xffffffffu, mloc[q], off));
    }
    if ((lane & 3) == 0) {
#pragma unroll
        for (int q = 0; q < 4; ++q) {
            int r = (q >> 1) * 16 + (q & 1) * 8 + (lane >> 2);
            rmax[r * 16 + w] = mloc[q];
        }
    }
    __syncthreads();
    if (tid < 32) {
        float m = -FLT_MAX;
#pragma unroll
        for (int w2 = 0; w2 < 16; ++w2) m = fmaxf(m, rmax[tid * 16 + w2]);
        marr[tid] = m;
    }
    __syncthreads();

    // candidates + exp + rowsum
    float sloc[4] = {0.f, 0.f, 0.f, 0.f};
#pragma unroll
    for (int mi = 0; mi < 2; ++mi) {
        int r0 = mi * 16 + (lane >> 2);
        float m0 = marr[r0], m1 = marr[r0 + 8];
        float t0 = m0 - FIX_MARGIN, t1 = m1 - FIX_MARGIN;
#pragma unroll
        for (int h = 0; h < 2; ++h)
#pragma unroll
            for (int ni = 0; ni < 4; ++ni) {
                int col = h * 512 + w * 32 + ni * 8 + (lane & 3) * 2;
                float* dd = d[mi][h][ni];
                if (dd[0] >= t0) { int sl = atomicAdd(&cnt[r0], 1);     if (sl < 16) candk[r0 * 16 + sl] = col; }
                if (dd[1] >= t0) { int sl = atomicAdd(&cnt[r0], 1);     if (sl < 16) candk[r0 * 16 + sl] = col + 1; }
                if (dd[2] >= t1) { int sl = atomicAdd(&cnt[r0 + 8], 1); if (sl < 16) candk[(r0 + 8) * 16 + sl] = col; }
                if (dd[3] >= t1) { int sl = atomicAdd(&cnt[r0 + 8], 1); if (sl < 16) candk[(r0 + 8) * 16 + sl] = col + 1; }
                dd[0] = __expf(dd[0] - m0);
                dd[1] = __expf(dd[1] - m0);
                dd[2] = __expf(dd[2] - m1);
                dd[3] = __expf(dd[3] - m1);
                sloc[mi * 2]     += dd[0] + dd[1];
                sloc[mi * 2 + 1] += dd[2] + dd[3];
            }
    }
#pragma unroll
    for (int q = 0; q < 4; ++q) {
#pragma unroll
        for (int off = 1; off <= 2; off <<= 1)
            sloc[q] += __shfl_xor_sync(0xffffffffu, sloc[q], off);
    }
    if ((lane & 3) == 0) {
#pragma unroll
        for (int q = 0; q < 4; ++q) {
            int r = (q >> 1) * 16 + (q & 1) * 8 + (lane >> 2);
            rsum[r * 16 + w] = sloc[q];
        }
    }
    __syncthreads();
    if (tid < 32) {
        float s = 0.f;
#pragma unroll
        for (int w2 = 0; w2 < 16; ++w2) s += rsum[tid * 16 + w2];
        invarr[tid] = 1.f / s;
        lsearr[tid] = (marr[tid] - x2arr[tid]) + __logf(s);
    }
    __syncthreads();

    // colsum(y) with per-row inv; col reduce (xor 4,8,16) and write partials
    float cy[16];
#pragma unroll
    for (int q = 0; q < 16; ++q) cy[q] = 0.f;
#pragma unroll
    for (int mi = 0; mi < 2; ++mi) {
        int r0 = mi * 16 + (lane >> 2);
        float i0 = invarr[r0], i1 = invarr[r0 + 8];
#pragma unroll
        for (int h = 0; h < 2; ++h)
#pragma unroll
            for (int ni = 0; ni < 4; ++ni) {
                float* dd = d[mi][h][ni];
                int ci = h * 8 + ni * 2;
                cy[ci]     += dd[0] * i0 + dd[2] * i1;
                cy[ci + 1] += dd[1] * i0 + dd[3] * i1;
            }
    }
#pragma unroll
    for (int q = 0; q < 16; ++q) {
#pragma unroll
        for (int off = 4; off <= 16; off <<= 1) {
            cy[q] += __shfl_xor_sync(0xffffffffu, cy[q], off);
            cv[q] += __shfl_xor_sync(0xffffffffu, cv[q], off);
        }
    }
    if (lane < 4) {
#pragma unroll
        for (int q = 0; q < 16; ++q) {
            int h = q >> 3, ni = (q >> 1) & 3, j = q & 1;
            int col = h * 512 + w * 32 + ni * 8 + lane * 2 + j;
            g_ypart[(size_t)cta * K_PROTO + col] = cy[q];
            g_vpart[(size_t)cta * K_PROTO + col] = cv[q];
        }
    }
    if (tid == 0) {
        double t = 0.0;
        for (int r = 0; r < 32; ++r) t += (double)lsearr[r];
        g_lsepart[cta] = t;
    }

    // exact argmax fixup + gather: warp w handles rows 2w, 2w+1
#pragma unroll
    for (int rr = 0; rr < 2; ++rr) {
        int r = w * 2 + rr;
        int grow = grow_base + r;
        int n = cnt[r]; if (n > 16) n = 16;
        const float4* Xr = (const float4*)(X + (size_t)grow * D_DIM);
        float4 xa = __ldg(&Xr[lane * 2]);
        float4 xb = __ldg(&Xr[lane * 2 + 1]);
        float x2r = x2arr[r];
        float vbest = -FLT_MAX;
        int kbest = 0;
        for (int ci = 0; ci < n; ++ci) {
            int k = candk[r * 16 + ci];
            const float4* Pr = (const float4*)(P + (size_t)k * D_DIM);
            float4 pa = __ldg(&Pr[lane * 2]);
            float4 pb = __ldg(&Pr[lane * 2 + 1]);
            float dot = xa.x * pa.x;
            dot = fmaf(xa.y, pa.y, dot);
            dot = fmaf(xa.z, pa.z, dot);
            dot = fmaf(xa.w, pa.w, dot);
            dot = fmaf(xb.x, pb.x, dot);
            dot = fmaf(xb.y, pb.y, dot);
            dot = fmaf(xb.z, pb.z, dot);
            dot = fmaf(xb.w, pb.w, dot);
#pragma unroll
            for (int off = 16; off; off >>= 1)
                dot += __shfl_xor_sync(0xffffffffu, dot, off);
            float vex = fmaf(2.f, dot, __ldg(&G[(size_t)grow * K_PROTO + k]))
                        - x2r - __ldg(&g_p2[k]);
            if (vex > vbest || (vex == vbest && k < kbest)) { vbest = vex; kbest = k; }
        }
        const float4* Pq = (const float4*)(P + (size_t)kbest * D_DIM);
        float4* Or = (float4*)(out + (size_t)grow * D_DIM);
        Or[lane * 2]     = __ldg(&Pq[lane * 2]);
        Or[lane * 2 + 1] = __ldg(&Pq[lane * 2 + 1]);
    }
}

// ===========================================================================
// K3: column reduce partials (double, deterministic)
// ===========================================================================
__global__ void colreduce_kernel()
{
    int k = blockIdx.x * 128 + threadIdx.x;
    double sy = 0.0, sv = 0.0;
    for (int bb = 0; bb < 1024; ++bb) {
        sy += (double)g_ypart[(size_t)bb * K_PROTO + k];
        sv += (double)g_vpart[(size_t)bb * K_PROTO + k];
    }
    g_coly[k] = sy;
    g_colv[k] = sv;
}

// ===========================================================================
// K4: final scalar
// ===========================================================================
__global__ void final_kernel(float* __restrict__ out, int out_size)
{
    const int t = threadIdx.x;
    double lse_total = 0.0;
    for (int q = 0; q < 1024; ++q) lse_total += g_lsepart[q];
    const double lse_mean = lse_total * (1.0 / N_ROWS);

    double t1 = 0.0, t2 = 0.0;
    for (int k = t; k < K_PROTO; k += 256) {
        double prior = g_coly[k] * (1.0 / N_ROWS) + 1e-6;
        double cmlp  = g_colv[k] * (1.0 / N_ROWS) - lse_mean;
        t1 += prior * log(prior);
        t2 += prior * cmlp;
    }
    __shared__ double r1[256];
    __shared__ double r2[256];
    r1[t] = t1; r2[t] = t2;
    __syncthreads();
    for (int off = 128; off; off >>= 1) {
        if (t < off) { r1[t] += r1[t + off]; r2[t] += r2[t + off]; }
        __syncthreads();
    }
    if (t == 0) {
        double capacity = r1[0] - r2[0];
        double ent      = -r1[0];
        out[out_size - 1] = (float)(capacity - 0.001 * ent);
    }
}

// ===========================================================================
extern "C" void kernel_launch(void* const* d_in, const int* in_sizes, int n_in,
                              void* d_out, int out_size)
{
    const float* X = (const float*)d_in[0];   // latents    [32768,256]
    const float* P = (const float*)d_in[1];   // prototypes [1024,256]
    const float* G = (const float*)d_in[2];   // gumbel     [32768,1024]
    float* out = (float*)d_out;

    cudaFuncSetAttribute(fused_kernel,
                         cudaFuncAttributeMaxDynamicSharedMemorySize, FUSED_SMEM);

    __nv_bfloat16 *xhi, *phi;
    float *x2, *p2;
    cudaGetSymbolAddress((void**)&xhi, g_xhi);
    cudaGetSymbolAddress((void**)&phi, g_phi);
    cudaGetSymbolAddress((void**)&x2, g_x2);
    cudaGetSymbolAddress((void**)&p2, g_p2);

    prep_kernel<<<N_ROWS / 8, 256>>>(X, xhi, x2, N_ROWS);
    prep_kernel<<<K_PROTO / 8, 256>>>(P, phi, p2, K_PROTO);
    fused_kernel<<<N_ROWS / 32, 512, FUSED_SMEM>>>(X, P, G, out);
    colreduce_kernel<<<K_PROTO / 128, 128>>>();
    final_kernel<<<1, 256>>>(out, out_size);
}